// round 7
// baseline (speedup 1.0000x reference)
#include <cuda_runtime.h>
#include <cstdint>

// P: [N=12, T=4096, D=2048] fp32; subgroup_indices: [2,6] (int32 or int64);
// out: [1, T, 2*D] fp32 ; out[t, s*D+d] = max_{g<6} P[idx[s*6+g], t, d]
//
// Pure HBM streaming: 403 MB read + 67 MB write, zero reuse. R3 showed we sit
// at ~84% DRAM. This round: persistent single-wave grid (148 SMs x 8 CTAs),
// grid-stride loop unrolled x2 -> 12 independent LDG.128 in flight per thread,
// no wave transitions, no CTA launch/retire churn. Base pointers hoisted.

#define T_FRAMES   4096
#define D_DIM      2048
#define D4         (D_DIM / 4)          // 512 float4 per (n,t) row
#define OUT_F4     (T_FRAMES * 2 * D4)  // 4,194,304 output float4
#define FRAME_F4   (2 * D4)             // 1024 float4 per output frame
#define TD4        ((long long)T_FRAMES * D4)

#define NUM_SMS    148
#define CTAS_PER_SM 8
#define GRID_CTAS  (NUM_SMS * CTAS_PER_SM)   // 1184
#define THREADS    256

__device__ __forceinline__ float4 f4max(float4 a, float4 b) {
    a.x = fmaxf(a.x, b.x);
    a.y = fmaxf(a.y, b.y);
    a.z = fmaxf(a.z, b.z);
    a.w = fmaxf(a.w, b.w);
    return a;
}

__global__ __launch_bounds__(THREADS) void subgroup_maxpool_kernel(
    const float4* __restrict__ P4,
    const int*    __restrict__ idx_words,
    float4*       __restrict__ out4)
{
    // Detect index dtype once: int64 arange -> words 0,0,1,0,... (word[1]==0)
    //                          int32 arange -> words 0,1,2,...   (word[1]==1)
    const bool is64 = (idx_words[1] == 0);

    // Hoist the 12 player base pointers (values are runtime data, layout fixed).
    const float4* base[12];
    #pragma unroll
    for (int j = 0; j < 12; ++j) {
        const int n = is64 ? idx_words[2 * j] : idx_words[j];
        base[j] = P4 + (long long)n * TD4;
    }

    const int stride = GRID_CTAS * THREADS;
    int i = blockIdx.x * THREADS + threadIdx.x;

    #pragma unroll 2
    for (; i < OUT_F4; i += stride) {
        const int t   = i >> 10;             // / FRAME_F4
        const int rem = i & (FRAME_F4 - 1);
        const int s   = rem >> 9;            // / D4
        const int d4  = rem & (D4 - 1);
        const long long col = (long long)t * D4 + d4;
        const int b = s * 6;

        float4 m = __ldcs(base[b + 0] + col);
        m = f4max(m, __ldcs(base[b + 1] + col));
        m = f4max(m, __ldcs(base[b + 2] + col));
        m = f4max(m, __ldcs(base[b + 3] + col));
        m = f4max(m, __ldcs(base[b + 4] + col));
        m = f4max(m, __ldcs(base[b + 5] + col));

        __stcs(&out4[i], m);
    }
}

extern "C" void kernel_launch(void* const* d_in, const int* in_sizes, int n_in,
                              void* d_out, int out_size)
{
    const float4* P4  = (const float4*)d_in[0];
    const int*    idx = (const int*)d_in[1];
    float4*       out = (float4*)d_out;

    subgroup_maxpool_kernel<<<GRID_CTAS, THREADS>>>(P4, idx, out);
}

// round 8
// speedup vs baseline: 1.1844x; 1.1844x over previous
#include <cuda_runtime.h>
#include <cstdint>

// P: [N=12, T=4096, D=2048] fp32; subgroup_indices: [2,6] (int32 or int64);
// out: [1, T, 2*D] fp32 ; out[t, s*D+d] = max_{g<6} P[idx[s*6+g], t, d]
//
// Pure HBM streaming (403 MB read + 67 MB write, zero reuse). Best so far:
// 69.7us @ 84% DRAM with one thread per output float4. This version maps one
// thread to one (t,d4) column and produces BOTH subgroup outputs:
//   - col == linear thread index i (no decode math at all)
//   - 12 independent LDG.128 per thread (2x MLP), all with compile-time
//     constant index-buffer offsets (no dynamic pointer array)
//   - 2 coalesced STG.128 per thread

#define T_FRAMES   4096
#define D_DIM      2048
#define D4         (D_DIM / 4)            // 512 float4 per (n,t) row
#define COLS       (T_FRAMES * D4)        // 2,097,152 (t,d4) columns
#define FRAME_F4   (2 * D4)               // 1024 float4 per output frame
#define TD4        ((long long)T_FRAMES * D4)
#define THREADS    256

__device__ __forceinline__ float4 f4max(float4 a, float4 b) {
    a.x = fmaxf(a.x, b.x);
    a.y = fmaxf(a.y, b.y);
    a.z = fmaxf(a.z, b.z);
    a.w = fmaxf(a.w, b.w);
    return a;
}

__global__ __launch_bounds__(THREADS) void subgroup_maxpool_kernel(
    const float4* __restrict__ P4,
    const int*    __restrict__ idx_words,
    float4*       __restrict__ out4)
{
    const int i = blockIdx.x * THREADS + threadIdx.x;
    if (i >= COLS) return;

    // Index dtype detect: int64 arange -> words 0,0,1,0,... (word[1]==0)
    //                     int32 arange -> words 0,1,2,...   (word[1]==1)
    const bool is64 = (idx_words[1] == 0);

    const long long col = i;   // col == t*D4 + d4 by construction

    // Issue all 12 loads (compile-time constant j per load -> no local array).
    float4 v[12];
    #pragma unroll
    for (int j = 0; j < 12; ++j) {
        const int n = is64 ? idx_words[2 * j] : idx_words[j];
        v[j] = __ldcs(P4 + (long long)n * TD4 + col);
    }

    // Reduce subgroup 0 (players idx[0..5]) and subgroup 1 (idx[6..11]).
    float4 m0 = f4max(f4max(f4max(v[0], v[1]), f4max(v[2], v[3])),
                      f4max(v[4], v[5]));
    float4 m1 = f4max(f4max(f4max(v[6], v[7]), f4max(v[8], v[9])),
                      f4max(v[10], v[11]));

    // out index: t*1024 + s*512 + d4, with t = i>>9, d4 = i&511.
    const int t  = i >> 9;
    const int d4 = i & (D4 - 1);
    const int o  = (t << 10) | d4;
    __stcs(&out4[o], m0);
    __stcs(&out4[o + D4], m1);
}

extern "C" void kernel_launch(void* const* d_in, const int* in_sizes, int n_in,
                              void* d_out, int out_size)
{
    const float4* P4  = (const float4*)d_in[0];
    const int*    idx = (const int*)d_in[1];
    float4*       out = (float4*)d_out;

    const int blocks = (COLS + THREADS - 1) / THREADS;  // 8192
    subgroup_maxpool_kernel<<<blocks, THREADS>>>(P4, idx, out);
}